// round 1
// baseline (speedup 1.0000x reference)
#include <cuda_runtime.h>
#include <cstdint>
#include <float.h>

// Problem dims (fixed by the problem)
#define NN_  8192   // search size
#define DD_  1024   // feature dim
#define QQ_  4096   // queries
#define DK_  512
#define DV_  256

// ---------------- scratch (static device globals: allocation-free) ----------
__device__ float g_K [(size_t)NN_ * DK_];          // 16 MB
__device__ float g_QK[(size_t)QQ_ * DK_];          // 8 MB
__device__ float g_P [(size_t)QQ_ * NN_];          // 128 MB (logits -> probs in place)
__device__ int   g_is64;

// ---------------- mask dtype probe ------------------------------------------
// mask values are 0/1. If the array is int64, every odd 32-bit word is 0.
// If int32, odd words are random 0/1 (P(all zero over 4096 samples) ~ 0).
__global__ void detect_mask_kernel(const unsigned int* __restrict__ mw)
{
    __shared__ int any;
    if (threadIdx.x == 0) any = 0;
    __syncthreads();
    int local = 0;
    for (int i = threadIdx.x; i < 4096; i += blockDim.x)
        if (mw[2 * i + 1] != 0u) local = 1;
    if (local) atomicOr(&any, 1);
    __syncthreads();
    if (threadIdx.x == 0) g_is64 = any ? 0 : 1;
}

// ---------------- generic fp32 tiled GEMM -----------------------------------
// C[M,N] = alpha * A[M,K] @ op(B),  op(B)=B[K,N] (BT=false) or B[N,K]^T (BT=true)
// All dims must divide the tile sizes (true for every instantiation below).
template<int BM, int BN, int BK, int TM, int TN, bool BT>
__global__ __launch_bounds__(256, 2)
void gemm_kernel(const float* __restrict__ A, const float* __restrict__ B,
                 float* __restrict__ C, int M, int N, int K, float alpha)
{
    constexpr int TX = BN / TN;
    constexpr int TY = BM / TM;
    constexpr int NT = TX * TY;   // must be 256

    __shared__ float As[BK][BM];
    __shared__ float Bs[BK][BN];

    const int tid = threadIdx.x;
    const int tx  = tid % TX;
    const int ty  = tid / TX;
    const int bm  = blockIdx.y * BM;
    const int bn  = blockIdx.x * BN;

    float acc[TM][TN];
    #pragma unroll
    for (int i = 0; i < TM; i++)
        #pragma unroll
        for (int j = 0; j < TN; j++) acc[i][j] = 0.f;

    for (int k0 = 0; k0 < K; k0 += BK) {
        // ---- load A tile (row-major, K contiguous) transposed into As[k][m]
        constexpr int A_F4 = BM * BK / 4;
        #pragma unroll
        for (int it = 0; it < A_F4 / NT; it++) {
            int i  = it * NT + tid;
            int m  = i / (BK / 4);
            int kk = (i % (BK / 4)) * 4;
            float4 v = *reinterpret_cast<const float4*>(
                &A[(size_t)(bm + m) * K + k0 + kk]);
            As[kk + 0][m] = v.x; As[kk + 1][m] = v.y;
            As[kk + 2][m] = v.z; As[kk + 3][m] = v.w;
        }
        // ---- load B tile
        if (BT) {
            // B is [N,K] row-major: load K-contiguous, transpose into Bs[k][n]
            constexpr int B_F4 = BN * BK / 4;
            #pragma unroll
            for (int it = 0; it < B_F4 / NT; it++) {
                int i  = it * NT + tid;
                int n  = i / (BK / 4);
                int kk = (i % (BK / 4)) * 4;
                float4 v = *reinterpret_cast<const float4*>(
                    &B[(size_t)(bn + n) * K + k0 + kk]);
                Bs[kk + 0][n] = v.x; Bs[kk + 1][n] = v.y;
                Bs[kk + 2][n] = v.z; Bs[kk + 3][n] = v.w;
            }
        } else {
            // B is [K,N] row-major: direct vector copy into Bs[k][n]
            constexpr int B_F4 = BK * BN / 4;
            #pragma unroll
            for (int it = 0; it < B_F4 / NT; it++) {
                int i  = it * NT + tid;
                int kk = i / (BN / 4);
                int nn = (i % (BN / 4)) * 4;
                *reinterpret_cast<float4*>(&Bs[kk][nn]) =
                    *reinterpret_cast<const float4*>(&B[(size_t)(k0 + kk) * N + bn + nn]);
            }
        }
        __syncthreads();

        #pragma unroll
        for (int k = 0; k < BK; k++) {
            float af[TM], bf[TN];
            #pragma unroll
            for (int i = 0; i < TM; i++) af[i] = As[k][ty * TM + i];
            #pragma unroll
            for (int j = 0; j < TN; j++) bf[j] = Bs[k][tx * TN + j];
            #pragma unroll
            for (int i = 0; i < TM; i++)
                #pragma unroll
                for (int j = 0; j < TN; j++)
                    acc[i][j] += af[i] * bf[j];
        }
        __syncthreads();
    }

    #pragma unroll
    for (int i = 0; i < TM; i++) {
        size_t crow = (size_t)(bm + ty * TM + i) * N + bn + tx * TN;
        #pragma unroll
        for (int j = 0; j < TN; j++)
            C[crow + j] = acc[i][j] * alpha;
    }
}

// ---------------- masked softmax (in place on g_P) --------------------------
__device__ __forceinline__ float warpMax(float v) {
    #pragma unroll
    for (int o = 16; o; o >>= 1) v = fmaxf(v, __shfl_xor_sync(0xFFFFFFFFu, v, o));
    return v;
}
__device__ __forceinline__ float warpSum(float v) {
    #pragma unroll
    for (int o = 16; o; o >>= 1) v += __shfl_xor_sync(0xFFFFFFFFu, v, o);
    return v;
}

__global__ __launch_bounds__(256)
void masked_softmax_kernel(float* __restrict__ P, const unsigned int* __restrict__ mw)
{
    const int row = blockIdx.x;
    const int tid = threadIdx.x;
    const int lane = tid & 31, wid = tid >> 5;
    const int is64 = g_is64;

    float4*       Pv = reinterpret_cast<float4*>(P + (size_t)row * NN_);
    const uint4*  M4 = reinterpret_cast<const uint4*>(mw);

    float4   xv[8];
    unsigned mk[8];
    float    mx = -FLT_MAX;

    #pragma unroll
    for (int i = 0; i < 8; i++) {
        const int idx = i * 256 + tid;           // float4 index in row (0..2047)
        float4 v = Pv[idx];
        unsigned m0, m1, m2, m3;
        if (is64) {
            uint4 a = M4[(size_t)row * 4096 + 2 * idx];
            uint4 b = M4[(size_t)row * 4096 + 2 * idx + 1];
            m0 = a.x | a.y; m1 = a.z | a.w; m2 = b.x | b.y; m3 = b.z | b.w;
        } else {
            uint4 a = M4[(size_t)row * 2048 + idx];
            m0 = a.x; m1 = a.y; m2 = a.z; m3 = a.w;
        }
        unsigned bits = (m0 ? 1u : 0u) | (m1 ? 2u : 0u) | (m2 ? 4u : 0u) | (m3 ? 8u : 0u);
        mk[i] = bits;
        xv[i] = v;
        if (bits & 1u) mx = fmaxf(mx, v.x);
        if (bits & 2u) mx = fmaxf(mx, v.y);
        if (bits & 4u) mx = fmaxf(mx, v.z);
        if (bits & 8u) mx = fmaxf(mx, v.w);
    }

    __shared__ float red[8];
    // block max
    mx = warpMax(mx);
    if (lane == 0) red[wid] = mx;
    __syncthreads();
    if (wid == 0) {
        float t = (lane < 8) ? red[lane] : -FLT_MAX;
        t = warpMax(t);
        if (lane == 0) red[0] = t;
    }
    __syncthreads();
    mx = red[0];
    __syncthreads();

    // exp + block sum
    float s = 0.f;
    #pragma unroll
    for (int i = 0; i < 8; i++) {
        float4 v = xv[i];
        v.x = (mk[i] & 1u) ? __expf(v.x - mx) : 0.f;
        v.y = (mk[i] & 2u) ? __expf(v.y - mx) : 0.f;
        v.z = (mk[i] & 4u) ? __expf(v.z - mx) : 0.f;
        v.w = (mk[i] & 8u) ? __expf(v.w - mx) : 0.f;
        s += v.x + v.y + v.z + v.w;
        xv[i] = v;
    }
    s = warpSum(s);
    if (lane == 0) red[wid] = s;
    __syncthreads();
    if (wid == 0) {
        float t = (lane < 8) ? red[lane] : 0.f;
        t = warpSum(t);
        if (lane == 0) red[0] = t;
    }
    __syncthreads();
    const float inv = 1.f / red[0];

    #pragma unroll
    for (int i = 0; i < 8; i++) {
        const int idx = i * 256 + tid;
        float4 v = xv[i];
        v.x *= inv; v.y *= inv; v.z *= inv; v.w *= inv;
        Pv[idx] = v;
    }
}

// ---------------- launch ----------------------------------------------------
extern "C" void kernel_launch(void* const* d_in, const int* in_sizes, int n_in,
                              void* d_out, int out_size)
{
    // Robust input mapping by element count (Wk before Wq in metadata order).
    const float* search_x = nullptr;
    const float* search_y = nullptr;
    const float* query_x  = nullptr;
    const unsigned int* maskw = nullptr;
    const float* Wk = nullptr;
    const float* Wq = nullptr;

    for (int i = 0; i < n_in; i++) {
        long long sz = in_sizes[i];
        if      (sz == (long long)NN_ * DD_)  search_x = (const float*)d_in[i];
        else if (sz == (long long)NN_ * DV_)  search_y = (const float*)d_in[i];
        else if (sz == (long long)QQ_ * DD_)  query_x  = (const float*)d_in[i];
        else if (sz == (long long)QQ_ * NN_)  maskw    = (const unsigned int*)d_in[i];
        else if (sz == (long long)DD_ * DK_) { if (!Wk) Wk = (const float*)d_in[i];
                                               else      Wq = (const float*)d_in[i]; }
    }
    float* out = (float*)d_out;

    float *gK, *gQK, *gP;
    cudaGetSymbolAddress((void**)&gK,  g_K);
    cudaGetSymbolAddress((void**)&gQK, g_QK);
    cudaGetSymbolAddress((void**)&gP,  g_P);

    const float scale = 0.044194173824159216f;  // 1/sqrt(512)

    // 0) mask dtype probe
    detect_mask_kernel<<<1, 256>>>(maskw);

    // 1) K = search_x @ Wk        [8192,1024]x[1024,512]
    {
        dim3 grid(DK_ / 64, NN_ / 128);
        gemm_kernel<128, 64, 16, 8, 4, false><<<grid, 256>>>(
            search_x, Wk, gK, NN_, DK_, DD_, 1.f);
    }
    // 2) QK = query_x @ Wq        [4096,1024]x[1024,512]
    {
        dim3 grid(DK_ / 64, QQ_ / 128);
        gemm_kernel<128, 64, 16, 8, 4, false><<<grid, 256>>>(
            query_x, Wq, gQK, QQ_, DK_, DD_, 1.f);
    }
    // 3) logits = scale * QK @ K^T   [4096,512]x[512,8192]
    {
        dim3 grid(NN_ / 128, QQ_ / 128);
        gemm_kernel<128, 128, 16, 8, 8, true><<<grid, 256>>>(
            gQK, gK, gP, QQ_, NN_, DK_, scale);
    }
    // 4) masked softmax over N (in place), mask read in native width
    masked_softmax_kernel<<<QQ_, 256>>>(gP, maskw);

    // 5) out = P @ search_y       [4096,8192]x[8192,256]
    {
        dim3 grid(DV_ / 64, QQ_ / 64);
        gemm_kernel<64, 64, 16, 4, 4, false><<<grid, 256>>>(
            gP, search_y, out, QQ_, DV_, NN_, 1.f);
    }
    (void)out_size; (void)n_in;
}

// round 5
// speedup vs baseline: 2.5123x; 2.5123x over previous
#include <cuda_runtime.h>
#include <cuda_bf16.h>
#include <cstdint>
#include <float.h>

// Problem dims
#define NN_  8192
#define DD_  1024
#define QQ_  4096
#define DK_  512
#define DV_  256
#define KSPLIT_PV 4

// ---------------- scratch (__device__ globals: allocation-free) -------------
__device__ __nv_bfloat16 g_Xhi [(size_t)NN_*DD_], g_Xlo [(size_t)NN_*DD_];
__device__ __nv_bfloat16 g_Qhi [(size_t)QQ_*DD_], g_Qlo [(size_t)QQ_*DD_];
__device__ __nv_bfloat16 g_WkThi[(size_t)DK_*DD_], g_WkTlo[(size_t)DK_*DD_];
__device__ __nv_bfloat16 g_WqThi[(size_t)DK_*DD_], g_WqTlo[(size_t)DK_*DD_];
__device__ __nv_bfloat16 g_Khi [(size_t)NN_*DK_], g_Klo [(size_t)NN_*DK_];
__device__ __nv_bfloat16 g_QKhi[(size_t)QQ_*DK_], g_QKlo[(size_t)QQ_*DK_];
__device__ float         g_L   [(size_t)QQ_*NN_];
__device__ __nv_bfloat16 g_Phi [(size_t)QQ_*NN_], g_Plo [(size_t)QQ_*NN_];
__device__ __nv_bfloat16 g_yThi[(size_t)DV_*NN_], g_yTlo[(size_t)DV_*NN_];
__device__ float         g_part[(size_t)KSPLIT_PV*QQ_*DV_];
__device__ int           g_is64;

// ---------------- base-ISA PTX helpers (legal on .target sm_103) ------------
__device__ __forceinline__ uint32_t smem_to_u32(const void* p) {
    uint32_t a;
    asm("{ .reg .u64 t; cvta.to.shared.u64 t, %1; cvt.u32.u64 %0, t; }"
        : "=r"(a) : "l"(p));
    return a;
}
__device__ __forceinline__ void cp_async16(uint32_t dst, const void* src) {
    asm volatile("cp.async.cg.shared.global [%0], [%1], 16;" :: "r"(dst), "l"(src));
}
#define CP_COMMIT() asm volatile("cp.async.commit_group;" ::: "memory")
template<int N> __device__ __forceinline__ void cp_wait() {
    asm volatile("cp.async.wait_group %0;" :: "n"(N) : "memory");
}
__device__ __forceinline__ void ldm_x4(uint32_t* r, uint32_t addr) {
    asm volatile("ldmatrix.sync.aligned.m8n8.x4.shared.b16 {%0,%1,%2,%3}, [%4];"
        : "=r"(r[0]), "=r"(r[1]), "=r"(r[2]), "=r"(r[3]) : "r"(addr));
}
__device__ __forceinline__ void mma_bf16(float* c, const uint32_t* a,
                                         uint32_t b0, uint32_t b1) {
    asm volatile(
        "mma.sync.aligned.m16n8k16.row.col.f32.bf16.bf16.f32 "
        "{%0,%1,%2,%3}, {%4,%5,%6,%7}, {%8,%9}, {%0,%1,%2,%3};"
        : "+f"(c[0]), "+f"(c[1]), "+f"(c[2]), "+f"(c[3])
        : "r"(a[0]), "r"(a[1]), "r"(a[2]), "r"(a[3]), "r"(b0), "r"(b1));
}

// ---------------- mma.sync split-bf16 GEMM ----------------------------------
// C[M,Nc] = alpha * A[M,K] · B[Nc,K]^T,  A ≈ Ahi+Alo, B ≈ Bhi+Blo (bf16).
// CTA tile 128x128x32, 8 warps (2x4), warp tile 64x32. All dims divide tiles.
#define SK      40                        // padded smem stride (bf16 elems)
#define TILEB   (128 * SK * 2)            // 10240 B: one 128x32 bf16 tile
#define STAGE_B (4 * TILEB)               // Ahi,Alo,Bhi,Blo per stage
#define GEMM_SMEM (2 * STAGE_B)           // double buffer: 81920 B

__device__ __forceinline__ void load_tile32(uint32_t sb32,
                                            const __nv_bfloat16* __restrict__ g,
                                            int ldg, int tid)
{
    #pragma unroll
    for (int it = 0; it < 2; it++) {
        int idx = it * 256 + tid;          // 512 x 16B chunks
        int row = idx >> 2, ch = idx & 3;
        cp_async16(sb32 + (uint32_t)(row * SK + ch * 8) * 2,
                   g + (size_t)row * ldg + ch * 8);
    }
}

template<bool OUT_SPLIT>
__global__ __launch_bounds__(256)
void gemm_mma(const __nv_bfloat16* __restrict__ Ahi, const __nv_bfloat16* __restrict__ Alo,
              const __nv_bfloat16* __restrict__ Bhi, const __nv_bfloat16* __restrict__ Blo,
              float* __restrict__ Cf,
              __nv_bfloat16* __restrict__ Chi, __nv_bfloat16* __restrict__ Clo,
              int M, int Nc, int K, int ksplit, float alpha)
{
    extern __shared__ char smem[];
    const int tid  = threadIdx.x;
    const int lane = tid & 31;
    const int w    = tid >> 5;
    const int bn   = blockIdx.x * 128;
    const int bm   = blockIdx.y * 128;
    const int z    = blockIdx.z;
    const int klen = K / ksplit;
    const int kbeg = z * klen;
    const int nkb  = klen / 32;
    const int wm   = (w & 1) * 64;
    const int wn   = (w >> 1) * 32;
    const uint32_t s32 = smem_to_u32(smem);

    const __nv_bfloat16* gAh = Ahi + (size_t)bm * K + kbeg;
    const __nv_bfloat16* gAl = Alo + (size_t)bm * K + kbeg;
    const __nv_bfloat16* gBh = Bhi + (size_t)bn * K + kbeg;
    const __nv_bfloat16* gBl = Blo + (size_t)bn * K + kbeg;

    float acc[4][4][4];
    #pragma unroll
    for (int i = 0; i < 4; i++)
        #pragma unroll
        for (int j = 0; j < 4; j++)
            #pragma unroll
            for (int r = 0; r < 4; r++) acc[i][j][r] = 0.f;

    // prologue: stage 0
    {
        uint32_t b = s32;
        load_tile32(b + 0*TILEB, gAh, K, tid);
        load_tile32(b + 1*TILEB, gAl, K, tid);
        load_tile32(b + 2*TILEB, gBh, K, tid);
        load_tile32(b + 3*TILEB, gBl, K, tid);
        CP_COMMIT();
    }

    const int lr = lane & 15;
    const int lc = (lane >> 4) * 8;

    for (int kb = 0; kb < nkb; kb++) {
        if (kb + 1 < nkb) {
            uint32_t b = s32 + ((kb + 1) & 1) * STAGE_B;
            const size_t ko = (size_t)(kb + 1) * 32;
            load_tile32(b + 0*TILEB, gAh + ko, K, tid);
            load_tile32(b + 1*TILEB, gAl + ko, K, tid);
            load_tile32(b + 2*TILEB, gBh + ko, K, tid);
            load_tile32(b + 3*TILEB, gBl + ko, K, tid);
            CP_COMMIT();
            cp_wait<1>();
        } else {
            cp_wait<0>();
        }
        __syncthreads();

        const uint32_t base = s32 + (kb & 1) * STAGE_B;
        const uint32_t Ah_s = base + 0*TILEB, Al_s = base + 1*TILEB;
        const uint32_t Bh_s = base + 2*TILEB, Bl_s = base + 3*TILEB;

        #pragma unroll
        for (int ki = 0; ki < 2; ki++) {
            uint32_t ah[4][4], al[4][4], bh[2][4], bl[2][4];
            #pragma unroll
            for (int im = 0; im < 4; im++) {
                uint32_t off = (uint32_t)((wm + im*16 + lr) * SK + ki*16 + lc) * 2;
                ldm_x4(ah[im], Ah_s + off);
                ldm_x4(al[im], Al_s + off);
            }
            #pragma unroll
            for (int in2 = 0; in2 < 2; in2++) {
                uint32_t off = (uint32_t)((wn + in2*16 + lr) * SK + ki*16 + lc) * 2;
                ldm_x4(bh[in2], Bh_s + off);
                ldm_x4(bl[in2], Bl_s + off);
            }
            #pragma unroll
            for (int im = 0; im < 4; im++)
                #pragma unroll
                for (int in = 0; in < 4; in++) {
                    const int i2 = in >> 1, s = in & 1;
                    mma_bf16(acc[im][in], ah[im], bh[i2][s], bh[i2][2+s]);
                    mma_bf16(acc[im][in], ah[im], bl[i2][s], bl[i2][2+s]);
                    mma_bf16(acc[im][in], al[im], bh[i2][s], bh[i2][2+s]);
                }
        }
        __syncthreads();
    }

    // epilogue
    const int er = lane >> 2;
    const int ec = (lane & 3) * 2;
    if (OUT_SPLIT) {
        #pragma unroll
        for (int im = 0; im < 4; im++)
            #pragma unroll
            for (int in = 0; in < 4; in++) {
                const int row0 = bm + wm + im*16 + er;
                const int col  = bn + wn + in*8 + ec;
                #pragma unroll
                for (int h = 0; h < 2; h++) {
                    const size_t off = (size_t)(row0 + h*8) * Nc + col;
                    float v0 = acc[im][in][2*h + 0] * alpha;
                    float v1 = acc[im][in][2*h + 1] * alpha;
                    __nv_bfloat16 h0 = __float2bfloat16(v0);
                    __nv_bfloat16 h1 = __float2bfloat16(v1);
                    __nv_bfloat16 l0 = __float2bfloat16(v0 - __bfloat162float(h0));
                    __nv_bfloat16 l1 = __float2bfloat16(v1 - __bfloat162float(h1));
                    *reinterpret_cast<__nv_bfloat162*>(Chi + off) = __nv_bfloat162(h0, h1);
                    *reinterpret_cast<__nv_bfloat162*>(Clo + off) = __nv_bfloat162(l0, l1);
                }
            }
    } else {
        float* Cp = Cf + (size_t)z * M * Nc;
        #pragma unroll
        for (int im = 0; im < 4; im++)
            #pragma unroll
            for (int in = 0; in < 4; in++) {
                const int row0 = bm + wm + im*16 + er;
                const int col  = bn + wn + in*8 + ec;
                #pragma unroll
                for (int h = 0; h < 2; h++) {
                    float2 v;
                    v.x = acc[im][in][2*h + 0] * alpha;
                    v.y = acc[im][in][2*h + 1] * alpha;
                    *reinterpret_cast<float2*>(
                        Cp + (size_t)(row0 + h*8) * Nc + col) = v;
                }
            }
    }
}

// ---------------- split / transpose prep -------------------------------------
__global__ __launch_bounds__(256)
void split_kernel(const float* __restrict__ in, __nv_bfloat16* __restrict__ hi,
                  __nv_bfloat16* __restrict__ lo, int n4)
{
    int i = blockIdx.x * blockDim.x + threadIdx.x;
    if (i >= n4) return;
    float4 v = reinterpret_cast<const float4*>(in)[i];
    __nv_bfloat16 h[4], l[4];
    float f[4] = {v.x, v.y, v.z, v.w};
    #pragma unroll
    for (int k = 0; k < 4; k++) {
        h[k] = __float2bfloat16(f[k]);
        l[k] = __float2bfloat16(f[k] - __bfloat162float(h[k]));
    }
    reinterpret_cast<__nv_bfloat162*>(hi)[2*i+0] = __nv_bfloat162(h[0], h[1]);
    reinterpret_cast<__nv_bfloat162*>(hi)[2*i+1] = __nv_bfloat162(h[2], h[3]);
    reinterpret_cast<__nv_bfloat162*>(lo)[2*i+0] = __nv_bfloat162(l[0], l[1]);
    reinterpret_cast<__nv_bfloat162*>(lo)[2*i+1] = __nv_bfloat162(l[2], l[3]);
}

// out[c*R + r] = in[r*C + c]; R,C multiples of 32
__global__ __launch_bounds__(256)
void split_transpose_kernel(const float* __restrict__ in,
                            __nv_bfloat16* __restrict__ hi,
                            __nv_bfloat16* __restrict__ lo, int R, int C)
{
    __shared__ float tile[32][33];
    const int cb = blockIdx.x * 32, rb = blockIdx.y * 32;
    const int tx = threadIdx.x & 31, ty0 = threadIdx.x >> 5;  // 32 x 8
    #pragma unroll
    for (int i = 0; i < 4; i++) {
        int ty = ty0 + i * 8;
        tile[ty][tx] = in[(size_t)(rb + ty) * C + cb + tx];
    }
    __syncthreads();
    #pragma unroll
    for (int i = 0; i < 4; i++) {
        int ty = ty0 + i * 8;
        float v = tile[tx][ty];
        __nv_bfloat16 h = __float2bfloat16(v);
        __nv_bfloat16 l = __float2bfloat16(v - __bfloat162float(h));
        size_t o = (size_t)(cb + ty) * R + rb + tx;
        hi[o] = h; lo[o] = l;
    }
}

// ---------------- mask dtype probe ------------------------------------------
__global__ void detect_mask_kernel(const unsigned int* __restrict__ mw)
{
    __shared__ int any;
    if (threadIdx.x == 0) any = 0;
    __syncthreads();
    int local = 0;
    for (int i = threadIdx.x; i < 4096; i += blockDim.x)
        if (mw[2 * i + 1] != 0u) local = 1;
    if (local) atomicOr(&any, 1);
    __syncthreads();
    if (threadIdx.x == 0) g_is64 = any ? 0 : 1;
}

// ---------------- masked softmax: fp32 logits -> split-bf16 probs -----------
__device__ __forceinline__ float warpMax(float v) {
    #pragma unroll
    for (int o = 16; o; o >>= 1) v = fmaxf(v, __shfl_xor_sync(0xFFFFFFFFu, v, o));
    return v;
}
__device__ __forceinline__ float warpSum(float v) {
    #pragma unroll
    for (int o = 16; o; o >>= 1) v += __shfl_xor_sync(0xFFFFFFFFu, v, o);
    return v;
}

__global__ __launch_bounds__(256)
void masked_softmax_kernel(const float* __restrict__ L,
                           const unsigned int* __restrict__ mw,
                           __nv_bfloat16* __restrict__ Phi,
                           __nv_bfloat16* __restrict__ Plo)
{
    const int row  = blockIdx.x;
    const int tid  = threadIdx.x;
    const int lane = tid & 31, wid = tid >> 5;
    const int is64 = g_is64;

    const float4* Lv = reinterpret_cast<const float4*>(L + (size_t)row * NN_);
    const uint4*  M4 = reinterpret_cast<const uint4*>(mw);

    float4   xv[8];
    unsigned mk[8];
    float    mx = -FLT_MAX;

    #pragma unroll
    for (int i = 0; i < 8; i++) {
        const int idx = i * 256 + tid;
        float4 v = Lv[idx];
        unsigned m0, m1, m2, m3;
        if (is64) {
            uint4 a = M4[(size_t)row * 4096 + 2 * idx];
            uint4 b = M4[(size_t)row * 4096 + 2 * idx + 1];
            m0 = a.x | a.y; m1 = a.z | a.w; m2 = b.x | b.y; m3 = b.z | b.w;
        } else {
            uint4 a = M4[(size_t)row * 2048 + idx];
            m0 = a.x; m1 = a.y; m2 = a.z; m3 = a.w;
        }
        unsigned bits = (m0 ? 1u : 0u) | (m1 ? 2u : 0u) | (m2 ? 4u : 0u) | (m3 ? 8u : 0u);
        mk[i] = bits;
        xv[i] = v;
        if (bits & 1u) mx = fmaxf(mx, v.x);
        if (bits & 2u) mx = fmaxf(mx, v.y);
        if (bits & 4u) mx = fmaxf(mx, v.z);
        if (bits & 8u) mx = fmaxf(mx, v.w);
    }

    __shared__ float red[8];
    mx = warpMax(mx);
    if (lane == 0) red[wid] = mx;
    __syncthreads();
    if (wid == 0) {
        float t = (lane < 8) ? red[lane] : -FLT_MAX;
        t = warpMax(t);
        if (lane == 0) red[0] = t;
    }
    __syncthreads();
    mx = red[0];
    __syncthreads();

    float s = 0.f;
    #pragma unroll
    for (int i = 0; i < 8; i++) {
        float4 v = xv[i];
        v.x = (mk[i] & 1u) ? __expf(v.x - mx) : 0.f;
        v.y = (mk[i] & 2u) ? __expf(v.y - mx) : 0.f;
        v.z = (mk[i] & 4u) ? __expf(v.z - mx) : 0.f;
        v.w = (mk[i] & 8u) ? __expf(v.w - mx) : 0.f;
        s += v.x + v.y + v.z + v.w;
        xv[i] = v;
    }
    s = warpSum(s);
    if (lane == 0) red[wid] = s;
    __syncthreads();
    if (wid == 0) {
        float t = (lane < 8) ? red[lane] : 0.f;
        t = warpSum(t);
        if (lane == 0) red[0] = t;
    }
    __syncthreads();
    const float inv = (red[0] > 0.f) ? (1.f / red[0]) : 0.f;

    const size_t rowoff = (size_t)row * NN_;
    #pragma unroll
    for (int i = 0; i < 8; i++) {
        const int idx = i * 256 + tid;
        float4 v = xv[i];
        float f[4] = {v.x * inv, v.y * inv, v.z * inv, v.w * inv};
        __nv_bfloat16 h[4], l[4];
        #pragma unroll
        for (int k = 0; k < 4; k++) {
            h[k] = __float2bfloat16(f[k]);
            l[k] = __float2bfloat16(f[k] - __bfloat162float(h[k]));
        }
        *reinterpret_cast<__nv_bfloat162*>(Phi + rowoff + idx * 4 + 0) = __nv_bfloat162(h[0], h[1]);
        *reinterpret_cast<__nv_bfloat162*>(Phi + rowoff + idx * 4 + 2) = __nv_bfloat162(h[2], h[3]);
        *reinterpret_cast<__nv_bfloat162*>(Plo + rowoff + idx * 4 + 0) = __nv_bfloat162(l[0], l[1]);
        *reinterpret_cast<__nv_bfloat162*>(Plo + rowoff + idx * 4 + 2) = __nv_bfloat162(l[2], l[3]);
    }
}

// ---------------- split-K reduction -----------------------------------------
__global__ __launch_bounds__(256)
void reduce4_kernel(const float* __restrict__ part, float* __restrict__ out, int n4)
{
    int i = blockIdx.x * blockDim.x + threadIdx.x;
    if (i >= n4) return;
    const float4* p = reinterpret_cast<const float4*>(part);
    const int stride4 = QQ_ * DV_ / 4;
    float4 a = p[i];
    float4 b = p[i + stride4];
    float4 c = p[i + 2 * stride4];
    float4 d = p[i + 3 * stride4];
    float4 r;
    r.x = (a.x + b.x) + (c.x + d.x);
    r.y = (a.y + b.y) + (c.y + d.y);
    r.z = (a.z + b.z) + (c.z + d.z);
    r.w = (a.w + b.w) + (c.w + d.w);
    reinterpret_cast<float4*>(out)[i] = r;
}

// ---------------- launch ----------------------------------------------------
extern "C" void kernel_launch(void* const* d_in, const int* in_sizes, int n_in,
                              void* d_out, int out_size)
{
    const float* search_x = nullptr;
    const float* search_y = nullptr;
    const float* query_x  = nullptr;
    const unsigned int* maskw = nullptr;
    const float* Wk = nullptr;
    const float* Wq = nullptr;

    for (int i = 0; i < n_in; i++) {
        long long sz = in_sizes[i];
        if      (sz == (long long)NN_ * DD_)  search_x = (const float*)d_in[i];
        else if (sz == (long long)NN_ * DV_)  search_y = (const float*)d_in[i];
        else if (sz == (long long)QQ_ * DD_)  query_x  = (const float*)d_in[i];
        else if (sz == (long long)QQ_ * NN_)  maskw    = (const unsigned int*)d_in[i];
        else if (sz == (long long)DD_ * DK_) { if (!Wk) Wk = (const float*)d_in[i];
                                               else      Wq = (const float*)d_in[i]; }
    }
    float* out = (float*)d_out;

    __nv_bfloat16 *Xhi,*Xlo,*Qhi,*Qlo,*WkThi,*WkTlo,*WqThi,*WqTlo;
    __nv_bfloat16 *Khi,*Klo,*QKhi,*QKlo,*Phi,*Plo,*yThi,*yTlo;
    float *Lp, *Pp;
    cudaGetSymbolAddress((void**)&Xhi,  g_Xhi);  cudaGetSymbolAddress((void**)&Xlo,  g_Xlo);
    cudaGetSymbolAddress((void**)&Qhi,  g_Qhi);  cudaGetSymbolAddress((void**)&Qlo,  g_Qlo);
    cudaGetSymbolAddress((void**)&WkThi,g_WkThi);cudaGetSymbolAddress((void**)&WkTlo,g_WkTlo);
    cudaGetSymbolAddress((void**)&WqThi,g_WqThi);cudaGetSymbolAddress((void**)&WqTlo,g_WqTlo);
    cudaGetSymbolAddress((void**)&Khi,  g_Khi);  cudaGetSymbolAddress((void**)&Klo,  g_Klo);
    cudaGetSymbolAddress((void**)&QKhi, g_QKhi); cudaGetSymbolAddress((void**)&QKlo, g_QKlo);
    cudaGetSymbolAddress((void**)&Phi,  g_Phi);  cudaGetSymbolAddress((void**)&Plo,  g_Plo);
    cudaGetSymbolAddress((void**)&yThi, g_yThi); cudaGetSymbolAddress((void**)&yTlo, g_yTlo);
    cudaGetSymbolAddress((void**)&Lp,   g_L);    cudaGetSymbolAddress((void**)&Pp,   g_part);

    cudaFuncSetAttribute(gemm_mma<false>,
        cudaFuncAttributeMaxDynamicSharedMemorySize, GEMM_SMEM);
    cudaFuncSetAttribute(gemm_mma<true>,
        cudaFuncAttributeMaxDynamicSharedMemorySize, GEMM_SMEM);

    const float scale = 0.044194173824159216f;  // 1/sqrt(512)

    // 0) probe + prep
    detect_mask_kernel<<<1, 256>>>(maskw);
    split_kernel<<<(NN_*DD_/4 + 255)/256, 256>>>(search_x, Xhi, Xlo, NN_*DD_/4);
    split_kernel<<<(QQ_*DD_/4 + 255)/256, 256>>>(query_x, Qhi, Qlo, QQ_*DD_/4);
    {
        dim3 g(DK_/32, DD_/32);
        split_transpose_kernel<<<g, 256>>>(Wk, WkThi, WkTlo, DD_, DK_);
        split_transpose_kernel<<<g, 256>>>(Wq, WqThi, WqTlo, DD_, DK_);
    }
    {
        dim3 g(DV_/32, NN_/32);
        split_transpose_kernel<<<g, 256>>>(search_y, yThi, yTlo, NN_, DV_);
    }

    // 1) keys = X @ Wk  -> split   [8192,512]
    gemm_mma<true><<<dim3(DK_/128, NN_/128, 1), 256, GEMM_SMEM>>>(
        Xhi, Xlo, WkThi, WkTlo, nullptr, Khi, Klo, NN_, DK_, DD_, 1, 1.f);
    // 2) qk = Qx @ Wq  -> split    [4096,512]
    gemm_mma<true><<<dim3(DK_/128, QQ_/128, 1), 256, GEMM_SMEM>>>(
        Qhi, Qlo, WqThi, WqTlo, nullptr, QKhi, QKlo, QQ_, DK_, DD_, 1, 1.f);
    // 3) logits = scale * qk @ keys^T -> fp32   [4096,8192]
    gemm_mma<false><<<dim3(NN_/128, QQ_/128, 1), 256, GEMM_SMEM>>>(
        QKhi, QKlo, Khi, Klo, Lp, nullptr, nullptr, QQ_, NN_, DK_, 1, scale);
    // 4) masked softmax -> split P
    masked_softmax_kernel<<<QQ_, 256>>>(Lp, maskw, Phi, Plo);
    // 5) out = P @ y   (split-K=4 partials)   [4096,256]
    gemm_mma<false><<<dim3(DV_/128, QQ_/128, KSPLIT_PV), 256, GEMM_SMEM>>>(
        Phi, Plo, yThi, yTlo, Pp, nullptr, nullptr, QQ_, DV_, NN_, KSPLIT_PV, 1.f);
    // 6) reduce partials
    reduce4_kernel<<<(QQ_*DV_/4 + 255)/256, 256>>>(Pp, out, QQ_*DV_/4);

    (void)out_size; (void)n_in;
}

// round 6
// speedup vs baseline: 2.5146x; 1.0009x over previous
#include <cuda_runtime.h>
#include <cuda_bf16.h>
#include <cstdint>
#include <float.h>

// Problem dims
#define NN_  8192
#define DD_  1024
#define QQ_  4096
#define DK_  512
#define DV_  256
#define KSPLIT_PV 4

// ---------------- scratch (__device__ globals: allocation-free) -------------
__device__ __nv_bfloat16 g_Xhi [(size_t)NN_*DD_], g_Xlo [(size_t)NN_*DD_];
__device__ __nv_bfloat16 g_Qhi [(size_t)QQ_*DD_], g_Qlo [(size_t)QQ_*DD_];
__device__ __nv_bfloat16 g_WkThi[(size_t)DK_*DD_], g_WkTlo[(size_t)DK_*DD_];
__device__ __nv_bfloat16 g_WqThi[(size_t)DK_*DD_], g_WqTlo[(size_t)DK_*DD_];
__device__ __nv_bfloat16 g_Khi [(size_t)NN_*DK_], g_Klo [(size_t)NN_*DK_];
__device__ __nv_bfloat16 g_QKhi[(size_t)QQ_*DK_], g_QKlo[(size_t)QQ_*DK_];
__device__ float         g_L   [(size_t)QQ_*NN_];
__device__ __nv_bfloat16 g_Phi [(size_t)QQ_*NN_], g_Plo [(size_t)QQ_*NN_];
__device__ __nv_bfloat16 g_yThi[(size_t)DV_*NN_], g_yTlo[(size_t)DV_*NN_];
__device__ float         g_part[(size_t)KSPLIT_PV*QQ_*DV_];
__device__ int           g_is64;

// ---------------- base-ISA PTX helpers (legal on .target sm_103) ------------
__device__ __forceinline__ uint32_t smem_to_u32(const void* p) {
    uint32_t a;
    asm("{ .reg .u64 t; cvta.to.shared.u64 t, %1; cvt.u32.u64 %0, t; }"
        : "=r"(a) : "l"(p));
    return a;
}
__device__ __forceinline__ void cp_async16(uint32_t dst, const void* src) {
    asm volatile("cp.async.cg.shared.global [%0], [%1], 16;" :: "r"(dst), "l"(src));
}
#define CP_COMMIT() asm volatile("cp.async.commit_group;" ::: "memory")
template<int N> __device__ __forceinline__ void cp_wait() {
    asm volatile("cp.async.wait_group %0;" :: "n"(N) : "memory");
}
__device__ __forceinline__ void ldm_x4(uint32_t* r, uint32_t addr) {
    asm volatile("ldmatrix.sync.aligned.m8n8.x4.shared.b16 {%0,%1,%2,%3}, [%4];"
        : "=r"(r[0]), "=r"(r[1]), "=r"(r[2]), "=r"(r[3]) : "r"(addr));
}
__device__ __forceinline__ void mma_bf16(float* c, const uint32_t* a,
                                         uint32_t b0, uint32_t b1) {
    asm volatile(
        "mma.sync.aligned.m16n8k16.row.col.f32.bf16.bf16.f32 "
        "{%0,%1,%2,%3}, {%4,%5,%6,%7}, {%8,%9}, {%0,%1,%2,%3};"
        : "+f"(c[0]), "+f"(c[1]), "+f"(c[2]), "+f"(c[3])
        : "r"(a[0]), "r"(a[1]), "r"(a[2]), "r"(a[3]), "r"(b0), "r"(b1));
}

// ---------------- mma.sync split-bf16 GEMM ----------------------------------
// C[M,Nc] = alpha * A[M,K] · B[Nc,K]^T,  A ≈ Ahi+Alo, B ≈ Bhi+Blo (bf16).
// CTA tile 128x128x32, 8 warps (2x4), warp tile 64x32. All dims divide tiles.
#define SK      40                        // padded smem stride (bf16 elems)
#define TILEB   (128 * SK * 2)            // 10240 B: one 128x32 bf16 tile
#define STAGE_B (4 * TILEB)               // Ahi,Alo,Bhi,Blo per stage
#define GEMM_SMEM (2 * STAGE_B)           // double buffer: 81920 B

__device__ __forceinline__ void load_tile32(uint32_t sb32,
                                            const __nv_bfloat16* __restrict__ g,
                                            int ldg, int tid)
{
    #pragma unroll
    for (int it = 0; it < 2; it++) {
        int idx = it * 256 + tid;          // 512 x 16B chunks
        int row = idx >> 2, ch = idx & 3;
        cp_async16(sb32 + (uint32_t)(row * SK + ch * 8) * 2,
                   g + (size_t)row * ldg + ch * 8);
    }
}

template<bool OUT_SPLIT>
__global__ __launch_bounds__(256)
void gemm_mma(const __nv_bfloat16* __restrict__ Ahi, const __nv_bfloat16* __restrict__ Alo,
              const __nv_bfloat16* __restrict__ Bhi, const __nv_bfloat16* __restrict__ Blo,
              float* __restrict__ Cf,
              __nv_bfloat16* __restrict__ Chi, __nv_bfloat16* __restrict__ Clo,
              int M, int Nc, int K, int ksplit, float alpha)
{
    extern __shared__ char smem[];
    const int tid  = threadIdx.x;
    const int lane = tid & 31;
    const int w    = tid >> 5;
    const int bn   = blockIdx.x * 128;
    const int bm   = blockIdx.y * 128;
    const int z    = blockIdx.z;
    const int klen = K / ksplit;
    const int kbeg = z * klen;
    const int nkb  = klen / 32;
    const int wm   = (w & 1) * 64;
    const int wn   = (w >> 1) * 32;
    const uint32_t s32 = smem_to_u32(smem);

    const __nv_bfloat16* gAh = Ahi + (size_t)bm * K + kbeg;
    const __nv_bfloat16* gAl = Alo + (size_t)bm * K + kbeg;
    const __nv_bfloat16* gBh = Bhi + (size_t)bn * K + kbeg;
    const __nv_bfloat16* gBl = Blo + (size_t)bn * K + kbeg;

    float acc[4][4][4];
    #pragma unroll
    for (int i = 0; i < 4; i++)
        #pragma unroll
        for (int j = 0; j < 4; j++)
            #pragma unroll
            for (int r = 0; r < 4; r++) acc[i][j][r] = 0.f;

    // prologue: stage 0
    {
        uint32_t b = s32;
        load_tile32(b + 0*TILEB, gAh, K, tid);
        load_tile32(b + 1*TILEB, gAl, K, tid);
        load_tile32(b + 2*TILEB, gBh, K, tid);
        load_tile32(b + 3*TILEB, gBl, K, tid);
        CP_COMMIT();
    }

    const int lr = lane & 15;
    const int lc = (lane >> 4) * 8;

    for (int kb = 0; kb < nkb; kb++) {
        if (kb + 1 < nkb) {
            uint32_t b = s32 + ((kb + 1) & 1) * STAGE_B;
            const size_t ko = (size_t)(kb + 1) * 32;
            load_tile32(b + 0*TILEB, gAh + ko, K, tid);
            load_tile32(b + 1*TILEB, gAl + ko, K, tid);
            load_tile32(b + 2*TILEB, gBh + ko, K, tid);
            load_tile32(b + 3*TILEB, gBl + ko, K, tid);
            CP_COMMIT();
            cp_wait<1>();
        } else {
            cp_wait<0>();
        }
        __syncthreads();

        const uint32_t base = s32 + (kb & 1) * STAGE_B;
        const uint32_t Ah_s = base + 0*TILEB, Al_s = base + 1*TILEB;
        const uint32_t Bh_s = base + 2*TILEB, Bl_s = base + 3*TILEB;

        #pragma unroll
        for (int ki = 0; ki < 2; ki++) {
            uint32_t ah[4][4], al[4][4], bh[2][4], bl[2][4];
            #pragma unroll
            for (int im = 0; im < 4; im++) {
                uint32_t off = (uint32_t)((wm + im*16 + lr) * SK + ki*16 + lc) * 2;
                ldm_x4(ah[im], Ah_s + off);
                ldm_x4(al[im], Al_s + off);
            }
            #pragma unroll
            for (int in2 = 0; in2 < 2; in2++) {
                uint32_t off = (uint32_t)((wn + in2*16 + lr) * SK + ki*16 + lc) * 2;
                ldm_x4(bh[in2], Bh_s + off);
                ldm_x4(bl[in2], Bl_s + off);
            }
            #pragma unroll
            for (int im = 0; im < 4; im++)
                #pragma unroll
                for (int in = 0; in < 4; in++) {
                    const int i2 = in >> 1, s = in & 1;
                    mma_bf16(acc[im][in], ah[im], bh[i2][s], bh[i2][2+s]);
                    mma_bf16(acc[im][in], ah[im], bl[i2][s], bl[i2][2+s]);
                    mma_bf16(acc[im][in], al[im], bh[i2][s], bh[i2][2+s]);
                }
        }
        __syncthreads();
    }

    // epilogue
    const int er = lane >> 2;
    const int ec = (lane & 3) * 2;
    if (OUT_SPLIT) {
        #pragma unroll
        for (int im = 0; im < 4; im++)
            #pragma unroll
            for (int in = 0; in < 4; in++) {
                const int row0 = bm + wm + im*16 + er;
                const int col  = bn + wn + in*8 + ec;
                #pragma unroll
                for (int h = 0; h < 2; h++) {
                    const size_t off = (size_t)(row0 + h*8) * Nc + col;
                    float v0 = acc[im][in][2*h + 0] * alpha;
                    float v1 = acc[im][in][2*h + 1] * alpha;
                    __nv_bfloat16 h0 = __float2bfloat16(v0);
                    __nv_bfloat16 h1 = __float2bfloat16(v1);
                    __nv_bfloat16 l0 = __float2bfloat16(v0 - __bfloat162float(h0));
                    __nv_bfloat16 l1 = __float2bfloat16(v1 - __bfloat162float(h1));
                    *reinterpret_cast<__nv_bfloat162*>(Chi + off) = __nv_bfloat162(h0, h1);
                    *reinterpret_cast<__nv_bfloat162*>(Clo + off) = __nv_bfloat162(l0, l1);
                }
            }
    } else {
        float* Cp = Cf + (size_t)z * M * Nc;
        #pragma unroll
        for (int im = 0; im < 4; im++)
            #pragma unroll
            for (int in = 0; in < 4; in++) {
                const int row0 = bm + wm + im*16 + er;
                const int col  = bn + wn + in*8 + ec;
                #pragma unroll
                for (int h = 0; h < 2; h++) {
                    float2 v;
                    v.x = acc[im][in][2*h + 0] * alpha;
                    v.y = acc[im][in][2*h + 1] * alpha;
                    *reinterpret_cast<float2*>(
                        Cp + (size_t)(row0 + h*8) * Nc + col) = v;
                }
            }
    }
}

// ---------------- split / transpose prep -------------------------------------
__global__ __launch_bounds__(256)
void split_kernel(const float* __restrict__ in, __nv_bfloat16* __restrict__ hi,
                  __nv_bfloat16* __restrict__ lo, int n4)
{
    int i = blockIdx.x * blockDim.x + threadIdx.x;
    if (i >= n4) return;
    float4 v = reinterpret_cast<const float4*>(in)[i];
    __nv_bfloat16 h[4], l[4];
    float f[4] = {v.x, v.y, v.z, v.w};
    #pragma unroll
    for (int k = 0; k < 4; k++) {
        h[k] = __float2bfloat16(f[k]);
        l[k] = __float2bfloat16(f[k] - __bfloat162float(h[k]));
    }
    reinterpret_cast<__nv_bfloat162*>(hi)[2*i+0] = __nv_bfloat162(h[0], h[1]);
    reinterpret_cast<__nv_bfloat162*>(hi)[2*i+1] = __nv_bfloat162(h[2], h[3]);
    reinterpret_cast<__nv_bfloat162*>(lo)[2*i+0] = __nv_bfloat162(l[0], l[1]);
    reinterpret_cast<__nv_bfloat162*>(lo)[2*i+1] = __nv_bfloat162(l[2], l[3]);
}

// out[c*R + r] = in[r*C + c]; R,C multiples of 32
__global__ __launch_bounds__(256)
void split_transpose_kernel(const float* __restrict__ in,
                            __nv_bfloat16* __restrict__ hi,
                            __nv_bfloat16* __restrict__ lo, int R, int C)
{
    __shared__ float tile[32][33];
    const int cb = blockIdx.x * 32, rb = blockIdx.y * 32;
    const int tx = threadIdx.x & 31, ty0 = threadIdx.x >> 5;  // 32 x 8
    #pragma unroll
    for (int i = 0; i < 4; i++) {
        int ty = ty0 + i * 8;
        tile[ty][tx] = in[(size_t)(rb + ty) * C + cb + tx];
    }
    __syncthreads();
    #pragma unroll
    for (int i = 0; i < 4; i++) {
        int ty = ty0 + i * 8;
        float v = tile[tx][ty];
        __nv_bfloat16 h = __float2bfloat16(v);
        __nv_bfloat16 l = __float2bfloat16(v - __bfloat162float(h));
        size_t o = (size_t)(cb + ty) * R + rb + tx;
        hi[o] = h; lo[o] = l;
    }
}

// ---------------- mask dtype probe ------------------------------------------
__global__ void detect_mask_kernel(const unsigned int* __restrict__ mw)
{
    __shared__ int any;
    if (threadIdx.x == 0) any = 0;
    __syncthreads();
    int local = 0;
    for (int i = threadIdx.x; i < 4096; i += blockDim.x)
        if (mw[2 * i + 1] != 0u) local = 1;
    if (local) atomicOr(&any, 1);
    __syncthreads();
    if (threadIdx.x == 0) g_is64 = any ? 0 : 1;
}

// ---------------- masked softmax: fp32 logits -> split-bf16 probs -----------
__device__ __forceinline__ float warpMax(float v) {
    #pragma unroll
    for (int o = 16; o; o >>= 1) v = fmaxf(v, __shfl_xor_sync(0xFFFFFFFFu, v, o));
    return v;
}
__device__ __forceinline__ float warpSum(float v) {
    #pragma unroll
    for (int o = 16; o; o >>= 1) v += __shfl_xor_sync(0xFFFFFFFFu, v, o);
    return v;
}

__global__ __launch_bounds__(256)
void masked_softmax_kernel(const float* __restrict__ L,
                           const unsigned int* __restrict__ mw,
                           __nv_bfloat16* __restrict__ Phi,
                           __nv_bfloat16* __restrict__ Plo)
{
    const int row  = blockIdx.x;
    const int tid  = threadIdx.x;
    const int lane = tid & 31, wid = tid >> 5;
    const int is64 = g_is64;

    const float4* Lv = reinterpret_cast<const float4*>(L + (size_t)row * NN_);
    const uint4*  M4 = reinterpret_cast<const uint4*>(mw);

    float4   xv[8];
    unsigned mk[8];
    float    mx = -FLT_MAX;

    #pragma unroll
    for (int i = 0; i < 8; i++) {
        const int idx = i * 256 + tid;
        float4 v = Lv[idx];
        unsigned m0, m1, m2, m3;
        if (is64) {
            uint4 a = M4[(size_t)row * 4096 + 2 * idx];
            uint4 b = M4[(size_t)row * 4096 + 2 * idx + 1];
            m0 = a.x | a.y; m1 = a.z | a.w; m2 = b.x | b.y; m3 = b.z | b.w;
        } else {
            uint4 a = M4[(size_t)row * 2048 + idx];
            m0 = a.x; m1 = a.y; m2 = a.z; m3 = a.w;
        }
        unsigned bits = (m0 ? 1u : 0u) | (m1 ? 2u : 0u) | (m2 ? 4u : 0u) | (m3 ? 8u : 0u);
        mk[i] = bits;
        xv[i] = v;
        if (bits & 1u) mx = fmaxf(mx, v.x);
        if (bits & 2u) mx = fmaxf(mx, v.y);
        if (bits & 4u) mx = fmaxf(mx, v.z);
        if (bits & 8u) mx = fmaxf(mx, v.w);
    }

    __shared__ float red[8];
    mx = warpMax(mx);
    if (lane == 0) red[wid] = mx;
    __syncthreads();
    if (wid == 0) {
        float t = (lane < 8) ? red[lane] : -FLT_MAX;
        t = warpMax(t);
        if (lane == 0) red[0] = t;
    }
    __syncthreads();
    mx = red[0];
    __syncthreads();

    float s = 0.f;
    #pragma unroll
    for (int i = 0; i < 8; i++) {
        float4 v = xv[i];
        v.x = (mk[i] & 1u) ? __expf(v.x - mx) : 0.f;
        v.y = (mk[i] & 2u) ? __expf(v.y - mx) : 0.f;
        v.z = (mk[i] & 4u) ? __expf(v.z - mx) : 0.f;
        v.w = (mk[i] & 8u) ? __expf(v.w - mx) : 0.f;
        s += v.x + v.y + v.z + v.w;
        xv[i] = v;
    }
    s = warpSum(s);
    if (lane == 0) red[wid] = s;
    __syncthreads();
    if (wid == 0) {
        float t = (lane < 8) ? red[lane] : 0.f;
        t = warpSum(t);
        if (lane == 0) red[0] = t;
    }
    __syncthreads();
    const float inv = (red[0] > 0.f) ? (1.f / red[0]) : 0.f;

    const size_t rowoff = (size_t)row * NN_;
    #pragma unroll
    for (int i = 0; i < 8; i++) {
        const int idx = i * 256 + tid;
        float4 v = xv[i];
        float f[4] = {v.x * inv, v.y * inv, v.z * inv, v.w * inv};
        __nv_bfloat16 h[4], l[4];
        #pragma unroll
        for (int k = 0; k < 4; k++) {
            h[k] = __float2bfloat16(f[k]);
            l[k] = __float2bfloat16(f[k] - __bfloat162float(h[k]));
        }
        *reinterpret_cast<__nv_bfloat162*>(Phi + rowoff + idx * 4 + 0) = __nv_bfloat162(h[0], h[1]);
        *reinterpret_cast<__nv_bfloat162*>(Phi + rowoff + idx * 4 + 2) = __nv_bfloat162(h[2], h[3]);
        *reinterpret_cast<__nv_bfloat162*>(Plo + rowoff + idx * 4 + 0) = __nv_bfloat162(l[0], l[1]);
        *reinterpret_cast<__nv_bfloat162*>(Plo + rowoff + idx * 4 + 2) = __nv_bfloat162(l[2], l[3]);
    }
}

// ---------------- split-K reduction -----------------------------------------
__global__ __launch_bounds__(256)
void reduce4_kernel(const float* __restrict__ part, float* __restrict__ out, int n4)
{
    int i = blockIdx.x * blockDim.x + threadIdx.x;
    if (i >= n4) return;
    const float4* p = reinterpret_cast<const float4*>(part);
    const int stride4 = QQ_ * DV_ / 4;
    float4 a = p[i];
    float4 b = p[i + stride4];
    float4 c = p[i + 2 * stride4];
    float4 d = p[i + 3 * stride4];
    float4 r;
    r.x = (a.x + b.x) + (c.x + d.x);
    r.y = (a.y + b.y) + (c.y + d.y);
    r.z = (a.z + b.z) + (c.z + d.z);
    r.w = (a.w + b.w) + (c.w + d.w);
    reinterpret_cast<float4*>(out)[i] = r;
}

// ---------------- launch ----------------------------------------------------
extern "C" void kernel_launch(void* const* d_in, const int* in_sizes, int n_in,
                              void* d_out, int out_size)
{
    const float* search_x = nullptr;
    const float* search_y = nullptr;
    const float* query_x  = nullptr;
    const unsigned int* maskw = nullptr;
    const float* Wk = nullptr;
    const float* Wq = nullptr;

    for (int i = 0; i < n_in; i++) {
        long long sz = in_sizes[i];
        if      (sz == (long long)NN_ * DD_)  search_x = (const float*)d_in[i];
        else if (sz == (long long)NN_ * DV_)  search_y = (const float*)d_in[i];
        else if (sz == (long long)QQ_ * DD_)  query_x  = (const float*)d_in[i];
        else if (sz == (long long)QQ_ * NN_)  maskw    = (const unsigned int*)d_in[i];
        else if (sz == (long long)DD_ * DK_) { if (!Wk) Wk = (const float*)d_in[i];
                                               else      Wq = (const float*)d_in[i]; }
    }
    float* out = (float*)d_out;

    __nv_bfloat16 *Xhi,*Xlo,*Qhi,*Qlo,*WkThi,*WkTlo,*WqThi,*WqTlo;
    __nv_bfloat16 *Khi,*Klo,*QKhi,*QKlo,*Phi,*Plo,*yThi,*yTlo;
    float *Lp, *Pp;
    cudaGetSymbolAddress((void**)&Xhi,  g_Xhi);  cudaGetSymbolAddress((void**)&Xlo,  g_Xlo);
    cudaGetSymbolAddress((void**)&Qhi,  g_Qhi);  cudaGetSymbolAddress((void**)&Qlo,  g_Qlo);
    cudaGetSymbolAddress((void**)&WkThi,g_WkThi);cudaGetSymbolAddress((void**)&WkTlo,g_WkTlo);
    cudaGetSymbolAddress((void**)&WqThi,g_WqThi);cudaGetSymbolAddress((void**)&WqTlo,g_WqTlo);
    cudaGetSymbolAddress((void**)&Khi,  g_Khi);  cudaGetSymbolAddress((void**)&Klo,  g_Klo);
    cudaGetSymbolAddress((void**)&QKhi, g_QKhi); cudaGetSymbolAddress((void**)&QKlo, g_QKlo);
    cudaGetSymbolAddress((void**)&Phi,  g_Phi);  cudaGetSymbolAddress((void**)&Plo,  g_Plo);
    cudaGetSymbolAddress((void**)&yThi, g_yThi); cudaGetSymbolAddress((void**)&yTlo, g_yTlo);
    cudaGetSymbolAddress((void**)&Lp,   g_L);    cudaGetSymbolAddress((void**)&Pp,   g_part);

    cudaFuncSetAttribute(gemm_mma<false>,
        cudaFuncAttributeMaxDynamicSharedMemorySize, GEMM_SMEM);
    cudaFuncSetAttribute(gemm_mma<true>,
        cudaFuncAttributeMaxDynamicSharedMemorySize, GEMM_SMEM);

    const float scale = 0.044194173824159216f;  // 1/sqrt(512)

    // 0) probe + prep
    detect_mask_kernel<<<1, 256>>>(maskw);
    split_kernel<<<(NN_*DD_/4 + 255)/256, 256>>>(search_x, Xhi, Xlo, NN_*DD_/4);
    split_kernel<<<(QQ_*DD_/4 + 255)/256, 256>>>(query_x, Qhi, Qlo, QQ_*DD_/4);
    {
        dim3 g(DK_/32, DD_/32);
        split_transpose_kernel<<<g, 256>>>(Wk, WkThi, WkTlo, DD_, DK_);
        split_transpose_kernel<<<g, 256>>>(Wq, WqThi, WqTlo, DD_, DK_);
    }
    {
        dim3 g(DV_/32, NN_/32);
        split_transpose_kernel<<<g, 256>>>(search_y, yThi, yTlo, NN_, DV_);
    }

    // 1) keys = X @ Wk  -> split   [8192,512]
    gemm_mma<true><<<dim3(DK_/128, NN_/128, 1), 256, GEMM_SMEM>>>(
        Xhi, Xlo, WkThi, WkTlo, nullptr, Khi, Klo, NN_, DK_, DD_, 1, 1.f);
    // 2) qk = Qx @ Wq  -> split    [4096,512]
    gemm_mma<true><<<dim3(DK_/128, QQ_/128, 1), 256, GEMM_SMEM>>>(
        Qhi, Qlo, WqThi, WqTlo, nullptr, QKhi, QKlo, QQ_, DK_, DD_, 1, 1.f);
    // 3) logits = scale * qk @ keys^T -> fp32   [4096,8192]
    gemm_mma<false><<<dim3(NN_/128, QQ_/128, 1), 256, GEMM_SMEM>>>(
        QKhi, QKlo, Khi, Klo, Lp, nullptr, nullptr, QQ_, NN_, DK_, 1, scale);
    // 4) masked softmax -> split P
    masked_softmax_kernel<<<QQ_, 256>>>(Lp, maskw, Phi, Plo);
    // 5) out = P @ y   (split-K=4 partials)   [4096,256]
    gemm_mma<false><<<dim3(DV_/128, QQ_/128, KSPLIT_PV), 256, GEMM_SMEM>>>(
        Phi, Plo, yThi, yTlo, Pp, nullptr, nullptr, QQ_, DV_, NN_, KSPLIT_PV, 1.f);
    // 6) reduce partials
    reduce4_kernel<<<(QQ_*DV_/4 + 255)/256, 256>>>(Pp, out, QQ_*DV_/4);

    (void)out_size; (void)n_in;
}